// round 10
// baseline (speedup 1.0000x reference)
#include <cuda_runtime.h>
#include <cuda_bf16.h>
#include <stdint.h>

// MinibatchDiscrimination: x[32,512,256] f32, T[256,512] f32 -> out[32,512,288] f32
// M = x @ T (bf16 tensor-core GEMM, cp.async-pipelined), pairwise L1 + guarded exp.

#define NSAMP   16384
#define FDIM    256
#define NCOLS   512
#define NK      32
#define KD      16
#define OUTF    288
#define SPB     32
#define NBLK    (NSAMP/SPB)  // 512
#define NT      256
#define KC      16           // K chunk
#define NCH     (FDIM/KC)    // 16
#define NBUF    3            // cp.async pipeline depth 2 -> 3 buffers

// smem layout (halfs):
//   xs  [32][264]  @ 0            (8448)
//   Ts0 [16][520]  @ 8448         (8320)
//   Ts1            @ 16768
//   Ts2            @ 25088
//   Ms  [32][520]  @ 0  (aliases xs+Ts0 after GEMM; 16640 <= 16768)
#define XST 264
#define TST 520
#define MST 520
#define XS_OFF 0
#define TS_OFF (32*XST)              // 8448
#define TSBUF  (KC*TST)              // 8320
#define SMEM_HALFS (TS_OFF + NBUF*TSBUF)
#define SMEM_BYTES (SMEM_HALFS*2)    // 66816 B -> 2 CTAs/SM

__device__ __nv_bfloat16 g_Tbf[FDIM * NCOLS];   // pre-converted T (256 KB)

__global__ void convT_kernel(const float* __restrict__ T) {
    int i = blockIdx.x * blockDim.x + threadIdx.x;   // float4 index
    float4 v = ((const float4*)T)[i];
    *(__nv_bfloat162*)&g_Tbf[i * 4]     = __floats2bfloat162_rn(v.x, v.y);
    *(__nv_bfloat162*)&g_Tbf[i * 4 + 2] = __floats2bfloat162_rn(v.z, v.w);
}

__device__ __forceinline__ unsigned int smem_addr(const void* p) {
    return (unsigned int)__cvta_generic_to_shared(p);
}
__device__ __forceinline__ void cp16(unsigned int dst, const void* src) {
    asm volatile("cp.async.cg.shared.global [%0], [%1], 16;" :: "r"(dst), "l"(src));
}
__device__ __forceinline__ void cp_commit() {
    asm volatile("cp.async.commit_group;");
}
__device__ __forceinline__ void ldmatrix_x4(unsigned int* r, unsigned int addr) {
    asm volatile("ldmatrix.sync.aligned.m8n8.x4.shared.b16 {%0,%1,%2,%3}, [%4];"
                 : "=r"(r[0]), "=r"(r[1]), "=r"(r[2]), "=r"(r[3]) : "r"(addr));
}
__device__ __forceinline__ void ldmatrix_x2_trans(unsigned int* r, unsigned int addr) {
    asm volatile("ldmatrix.sync.aligned.m8n8.x2.trans.shared.b16 {%0,%1}, [%2];"
                 : "=r"(r[0]), "=r"(r[1]) : "r"(addr));
}
__device__ __forceinline__ void mma_bf16(float* c, const unsigned int* a, const unsigned int* b) {
    asm volatile("mma.sync.aligned.m16n8k16.row.col.f32.bf16.bf16.f32 "
                 "{%0,%1,%2,%3}, {%4,%5,%6,%7}, {%8,%9}, {%0,%1,%2,%3};"
                 : "+f"(c[0]), "+f"(c[1]), "+f"(c[2]), "+f"(c[3])
                 : "r"(a[0]), "r"(a[1]), "r"(a[2]), "r"(a[3]), "r"(b[0]), "r"(b[1]));
}

extern __shared__ __nv_bfloat16 sm[];

__global__ void __launch_bounds__(NT, 2) mbd_kernel(
    const float* __restrict__ x,
    float* __restrict__ out)
{
    __nv_bfloat16* xs = sm + XS_OFF;
    __nv_bfloat16* Ms = sm;            // aliases xs+Ts0 (dead at epilogue)

    const int t = threadIdx.x;
    const int warp = t >> 5;
    const int lane = t & 31;
    const long sbase = (long)blockIdx.x * SPB;

    // ---- prefetch T chunks 0,1 via cp.async (depth 2) ----
    // chunk = 16 rows x 512 halfs = 1024 granules of 16B; 4 per thread
    {
        #pragma unroll
        for (int c = 0; c < 2; c++) {
            const char* src = (const char*)(g_Tbf + (long)c * KC * NCOLS);
            unsigned int dst = smem_addr(sm + TS_OFF + (c % NBUF) * TSBUF);
            #pragma unroll
            for (int i = 0; i < 4; i++) {
                int g = t + i * NT;             // 0..1023
                int r = g >> 6, c16 = g & 63;
                cp16(dst + (r * TST + c16 * 8) * 2, src + r * 1024 + c16 * 16);
            }
            cp_commit();
        }
    }

    // ---- stage x: gmem -> out (copy) and -> xs (bf16) ----
    {
        const float4* xg = (const float4*)(x + sbase * FDIM);
        #pragma unroll
        for (int i = 0; i < 8; i++) {
            int idx = t + i * NT;
            int s = idx >> 6, c4 = idx & 63;
            float4 v = xg[idx];
            *(float4*)&out[(sbase + s) * OUTF + c4 * 4] = v;
            *(__nv_bfloat162*)&xs[s * XST + c4 * 4]     = __floats2bfloat162_rn(v.x, v.y);
            *(__nv_bfloat162*)&xs[s * XST + c4 * 4 + 2] = __floats2bfloat162_rn(v.z, v.w);
        }
    }

    // ---- GEMM mainloop: warp w -> rows 0..31 x cols [w*64, w*64+64) ----
    const int n0 = warp * 64;
    float acc[2][8][4];
    #pragma unroll
    for (int mt = 0; mt < 2; mt++)
        #pragma unroll
        for (int nt = 0; nt < 8; nt++)
            #pragma unroll
            for (int j = 0; j < 4; j++) acc[mt][nt][j] = 0.f;

    const int arow = lane & 15;
    const int acg  = lane >> 4;

    #pragma unroll 1
    for (int ch = 0; ch < NCH; ch++) {
        if (ch < NCH - 1) asm volatile("cp.async.wait_group 1;");
        else              asm volatile("cp.async.wait_group 0;");
        __syncthreads();   // chunk ch visible to all; all warps done with buf[(ch-1)%3]

        if (ch + 2 < NCH) {
            const int c = ch + 2;
            const char* src = (const char*)(g_Tbf + (long)c * KC * NCOLS);
            unsigned int dst = smem_addr(sm + TS_OFF + (c % NBUF) * TSBUF);
            #pragma unroll
            for (int i = 0; i < 4; i++) {
                int g = t + i * NT;
                int r = g >> 6, c16 = g & 63;
                cp16(dst + (r * TST + c16 * 8) * 2, src + r * 1024 + c16 * 16);
            }
            cp_commit();
        }

        const __nv_bfloat16* Tb = sm + TS_OFF + (ch % NBUF) * TSBUF;
        unsigned int a[2][4];
        ldmatrix_x4(a[0], smem_addr(&xs[arow        * XST + ch * KC + acg * 8]));
        ldmatrix_x4(a[1], smem_addr(&xs[(16 + arow) * XST + ch * KC + acg * 8]));
        #pragma unroll
        for (int nt = 0; nt < 8; nt++) {
            unsigned int b[2];
            ldmatrix_x2_trans(b, smem_addr(&Tb[arow * TST + n0 + nt * 8]));
            mma_bf16(acc[0][nt], a[0], b);
            mma_bf16(acc[1][nt], a[1], b);
        }
    }

    // ---- store M (bf16) to smem (Ms aliases xs+Ts0; all reads done) ----
    __syncthreads();
    {
        const int r = lane >> 2, c = (lane & 3) * 2;
        #pragma unroll
        for (int mt = 0; mt < 2; mt++)
            #pragma unroll
            for (int nt = 0; nt < 8; nt++) {
                *(__nv_bfloat162*)&Ms[(mt * 16 + r)     * MST + n0 + nt * 8 + c] =
                    __floats2bfloat162_rn(acc[mt][nt][0], acc[mt][nt][1]);
                *(__nv_bfloat162*)&Ms[(mt * 16 + r + 8) * MST + n0 + nt * 8 + c] =
                    __floats2bfloat162_rn(acc[mt][nt][2], acc[mt][nt][3]);
            }
    }
    __syncthreads();

    // ---- pairwise L1 + guarded exp; warp w handles samples w*4..w*4+3, lane = k1 ----
    #pragma unroll
    for (int si = 0; si < 4; si++) {
        const int s = warp * 4 + si;
        const __nv_bfloat16* Mrow = &Ms[s * MST];

        __align__(16) __nv_bfloat162 v[8];
        *(uint4*)&v[0] = *(const uint4*)&Mrow[lane * KD];
        *(uint4*)&v[4] = *(const uint4*)&Mrow[lane * KD + 8];

        __nv_bfloat162 a8[8];
        const __nv_bfloat162 z2 = __floats2bfloat162_rn(0.f, 0.f);
        #pragma unroll
        for (int j = 0; j < 8; j++) a8[j] = z2;

        #pragma unroll 4
        for (int k2 = 0; k2 < NK; k2++) {
            __align__(16) __nv_bfloat162 m[8];
            *(uint4*)&m[0] = *(const uint4*)&Mrow[k2 * KD];       // broadcast
            *(uint4*)&m[4] = *(const uint4*)&Mrow[k2 * KD + 8];
            #pragma unroll
            for (int j = 0; j < 8; j++)
                a8[j] = __hadd2(a8[j], __habs2(__hsub2(m[j], v[j])));
        }

        float av[16];
        float mn = 1e30f;
        #pragma unroll
        for (int j = 0; j < 8; j++) {
            float2 f = __bfloat1622float2(a8[j]);
            av[2 * j] = f.x; av[2 * j + 1] = f.y;
            mn = fminf(mn, fminf(f.x, f.y));
        }

        float facc = 0.f;
        if (__any_sync(0xffffffffu, mn < 100.0f)) {   // exp(-100)=3.7e-44: faithful, ~never taken
            #pragma unroll
            for (int d = 0; d < 16; d++)
                if (av[d] < 100.0f) facc += __expf(-av[d]);
        }
        out[(sbase + s) * OUTF + FDIM + lane] = facc;
    }
}

extern "C" void kernel_launch(void* const* d_in, const int* in_sizes, int n_in,
                              void* d_out, int out_size)
{
    const float* x = (const float*)d_in[0];
    const float* T = (const float*)d_in[1];
    if (n_in >= 2 && in_sizes[0] < in_sizes[1]) {
        const float* tmp = x; x = T; T = tmp;
    }
    float* out = (float*)d_out;

    cudaFuncSetAttribute(mbd_kernel,
                         cudaFuncAttributeMaxDynamicSharedMemorySize,
                         SMEM_BYTES);

    convT_kernel<<<(FDIM * NCOLS / 4) / NT, NT>>>(T);
    mbd_kernel<<<NBLK, NT, SMEM_BYTES>>>(x, out);
}